// round 10
// baseline (speedup 1.0000x reference)
#include <cuda_runtime.h>
#include <cstdint>

#define Nn 50000
#define Ee 500000
#define Rr 200
#define D  128
#define SLOPE 0.01f

// ---------------- device scratch (no allocations allowed) ----------------
__device__ float g_Xa[Nn * D];     // x @ W1a
__device__ float g_Xb[Nn * D];     // x @ W1b + b1
__device__ float g_Relc[Rr * D];   // rel @ W1c
__device__ float g_sa[Nn];         // Xa . w2
__device__ float g_sb[Nn];         // Xb . w2
__device__ float g_sr[Rr];         // Relc . w2
__device__ float g_ex[Ee];         // leaky-relu logits b
__device__ float g_denom[Nn];
__device__ int   g_bmax[Nn];       // encoded float max

// monotone float<->int encoding for atomicMax over signed floats
__device__ __forceinline__ int fenc(float f) {
    int i = __float_as_int(f);
    return (i >= 0) ? i : (i ^ 0x7FFFFFFF);
}
__device__ __forceinline__ float fdec(int i) {
    return __int_as_float((i >= 0) ? i : (i ^ 0x7FFFFFFF));
}

__device__ __forceinline__ void red_add_v4(float* addr, float4 v) {
    asm volatile("red.global.add.v4.f32 [%0], {%1,%2,%3,%4};"
                 :: "l"(addr), "f"(v.x), "f"(v.y), "f"(v.z), "f"(v.w)
                 : "memory");
}

// ---------------- init: denom=0, bmax=INT_MIN ----------------
__global__ void init_kernel() {
    int i = blockIdx.x * blockDim.x + threadIdx.x;
    if (i < Nn) {
        g_denom[i] = 0.0f;
        g_bmax[i]  = int(0x80000000);
    }
}

// ---------------- GEMM: Xa / Xb = x @ W1[half] (+ b1 for half=1) ----------
// 128x128 tile per block, 256 threads, 8x8 microtile, BK=16.
// Epilogue also produces sa/sb = row . w2 via 16-lane shfl reduction.
__global__ __launch_bounds__(256) void gemm_xab(const float* __restrict__ x,
                                                const float* __restrict__ W1,
                                                const float* __restrict__ b1,
                                                const float* __restrict__ w2) {
    const int half = blockIdx.y;           // 0 -> Xa, 1 -> Xb
    const int rowBase = blockIdx.x * 128;
    __shared__ float xs[16][128];
    __shared__ float ws[16][128];

    float acc[8][8];
#pragma unroll
    for (int i = 0; i < 8; i++)
#pragma unroll
        for (int j = 0; j < 8; j++) acc[i][j] = 0.0f;

    const int tid = threadIdx.x;
    const int tx = tid & 15;               // col group (8 cols each)
    const int ty = tid >> 4;               // row group (8 rows each)

    // x-tile load mapping: 128 rows x 16 k as float4 along k
    const int lm = tid >> 2;               // row 0..63 (then +64)
    const int lk = (tid & 3) * 4;          // k offset 0,4,8,12
    // w-tile load mapping: 16 k x 128 cols as float4 along col
    const int wk = tid >> 5;               // k 0..7 (then +8)
    const int wc = (tid & 31) * 4;         // col

    const float* Wbase = W1 + (size_t)half * 128 * 128;

    for (int k0 = 0; k0 < 128; k0 += 16) {
#pragma unroll
        for (int i = 0; i < 2; i++) {
            int m = lm + i * 64;
            int row = rowBase + m;
            float4 v = make_float4(0.f, 0.f, 0.f, 0.f);
            if (row < Nn) v = *(const float4*)(x + (size_t)row * 128 + k0 + lk);
            xs[lk + 0][m] = v.x;
            xs[lk + 1][m] = v.y;
            xs[lk + 2][m] = v.z;
            xs[lk + 3][m] = v.w;
        }
#pragma unroll
        for (int i = 0; i < 2; i++) {
            int k = wk + i * 8;
            *(float4*)&ws[k][wc] = *(const float4*)(Wbase + (size_t)(k0 + k) * 128 + wc);
        }
        __syncthreads();
#pragma unroll
        for (int k = 0; k < 16; k++) {
            float a[8], b[8];
            *(float4*)&a[0] = *(float4*)&xs[k][ty * 8];
            *(float4*)&a[4] = *(float4*)&xs[k][ty * 8 + 4];
            *(float4*)&b[0] = *(float4*)&ws[k][tx * 8];
            *(float4*)&b[4] = *(float4*)&ws[k][tx * 8 + 4];
#pragma unroll
            for (int i = 0; i < 8; i++)
#pragma unroll
                for (int j = 0; j < 8; j++) acc[i][j] += a[i] * b[j];
        }
        __syncthreads();
    }

    // Epilogue: store rows; fuse per-row dot with w2 (sa/sb).
    float* outp = half ? g_Xb : g_Xa;
    float* sp   = half ? g_sb : g_sa;
    float w2c[8], b1c[8];
#pragma unroll
    for (int j = 0; j < 8; j += 4) {
        *(float4*)&w2c[j] = *(const float4*)(w2 + tx * 8 + j);
        *(float4*)&b1c[j] = *(const float4*)(b1 + tx * 8 + j);
    }
#pragma unroll
    for (int i = 0; i < 8; i++) {
        int row = rowBase + ty * 8 + i;
        float p = 0.f;
        if (row < Nn) {
            float v[8];
#pragma unroll
            for (int j = 0; j < 8; j++) {
                v[j] = acc[i][j];
                if (half) v[j] += b1c[j];
                p += v[j] * w2c[j];
            }
            *(float4*)&outp[(size_t)row * 128 + tx * 8]     = *(float4*)&v[0];
            *(float4*)&outp[(size_t)row * 128 + tx * 8 + 4] = *(float4*)&v[4];
        }
        // 16-lane butterfly within half-warp (tx = tid&15, same warp half)
#pragma unroll
        for (int o = 1; o < 16; o <<= 1) p += __shfl_xor_sync(0xFFFFFFFFu, p, o);
        if (tx == 0 && row < Nn) sp[row] = p;
    }
}

// ---------------- Relc = rel @ W1c, sr = Relc . w2 ----------------
__global__ void relc_kernel(const float* __restrict__ rel,
                            const float* __restrict__ W1,
                            const float* __restrict__ w2) {
    const int r = blockIdx.x;
    const int j = threadIdx.x;              // 128 threads
    __shared__ float rrow[128];
    __shared__ float red[128];
    rrow[j] = rel[(size_t)r * 128 + j];
    __syncthreads();
    const float* Wc = W1 + (size_t)256 * 128;
    float acc = 0.f;
#pragma unroll 8
    for (int k = 0; k < 128; k++) acc += rrow[k] * Wc[(size_t)k * 128 + j];
    g_Relc[(size_t)r * 128 + j] = acc;
    red[j] = acc * w2[j];
    __syncthreads();
    for (int s = 64; s > 0; s >>= 1) {
        if (j < s) red[j] += red[j + s];
        __syncthreads();
    }
    if (j == 0) g_sr[r] = red[0];
}

// ---------------- Pass A: logits + segment max (4 edges per thread) --------
__global__ void logits_max(const int* __restrict__ src, const int* __restrict__ dst,
                           const int* __restrict__ et) {
    int q = blockIdx.x * blockDim.x + threadIdx.x;   // quad index
    if (q >= Ee / 4) return;
    int4 s4 = ((const int4*)src)[q];
    int4 d4 = ((const int4*)dst)[q];
    int4 t4 = ((const int4*)et)[q];
    float b[4];
    {
        float v0 = g_sa[s4.x] + g_sb[d4.x] + g_sr[t4.x];
        float v1 = g_sa[s4.y] + g_sb[d4.y] + g_sr[t4.y];
        float v2 = g_sa[s4.z] + g_sb[d4.z] + g_sr[t4.z];
        float v3 = g_sa[s4.w] + g_sb[d4.w] + g_sr[t4.w];
        b[0] = (v0 > 0.f) ? v0 : SLOPE * v0;
        b[1] = (v1 > 0.f) ? v1 : SLOPE * v1;
        b[2] = (v2 > 0.f) ? v2 : SLOPE * v2;
        b[3] = (v3 > 0.f) ? v3 : SLOPE * v3;
    }
    ((float4*)g_ex)[q] = make_float4(b[0], b[1], b[2], b[3]);
    atomicMax(&g_bmax[d4.x], fenc(b[0]));
    atomicMax(&g_bmax[d4.y], fenc(b[1]));
    atomicMax(&g_bmax[d4.z], fenc(b[2]));
    atomicMax(&g_bmax[d4.w], fenc(b[3]));
}

// ---------------- Pass B+C fused: exp + denom sum + weighted scatter -------
// One warp per edge. All lanes recompute ex (broadcast loads, MUFU is free
// against the memory time); lane 0 accumulates the softmax denominator.
__global__ void scatter_kernel(const int* __restrict__ src, const int* __restrict__ dst,
                               const int* __restrict__ et, float* __restrict__ out) {
    int e = (blockIdx.x * blockDim.x + threadIdx.x) >> 5;
    int lane = threadIdx.x & 31;
    if (e >= Ee) return;
    int s = src[e], d = dst[e], t = et[e];
    float b = g_ex[e];
    float m = fdec(g_bmax[d]);
    float w = expf(b - m);
    if (lane == 0) atomicAdd(&g_denom[d], w);
    float4 xa = *(const float4*)&g_Xa[(size_t)s * 128 + lane * 4];
    float4 rc = *(const float4*)&g_Relc[(size_t)t * 128 + lane * 4];
    float4 v = make_float4(w * (xa.x + rc.x), w * (xa.y + rc.y),
                           w * (xa.z + rc.z), w * (xa.w + rc.w));
    red_add_v4(&out[(size_t)d * 128 + lane * 4], v);
}

// ---------------- finalize: out = leaky(out/denom + Xb) ----------------
__global__ void finalize_kernel(float* __restrict__ out) {
    int idx = blockIdx.x * blockDim.x + threadIdx.x;
    if (idx >= Nn * D) return;
    int n = idx >> 7;
    float dn = g_denom[n];
    float o = 0.f;
    if (dn > 0.f) {
        o = out[idx] / dn + g_Xb[idx];
        o = (o > 0.f) ? o : SLOPE * o;
    }
    out[idx] = o;
}

// ---------------- host launcher ----------------
extern "C" void kernel_launch(void* const* d_in, const int* in_sizes, int n_in,
                              void* d_out, int out_size) {
    const float* x   = (const float*)d_in[0];
    const float* rel = (const float*)d_in[1];
    const float* W1  = (const float*)d_in[2];
    const float* b1  = (const float*)d_in[3];
    const float* w2  = (const float*)d_in[4];
    const int* eidx  = (const int*)d_in[5];
    const int* et    = (const int*)d_in[6];
    const int* src = eidx;
    const int* dst = eidx + Ee;
    float* out = (float*)d_out;

    cudaMemsetAsync(d_out, 0, (size_t)Nn * D * sizeof(float));
    init_kernel<<<(Nn + 255) / 256, 256>>>();
    gemm_xab<<<dim3((Nn + 127) / 128, 2), 256>>>(x, W1, b1, w2);
    relc_kernel<<<Rr, 128>>>(rel, W1, w2);
    logits_max<<<(Ee / 4 + 255) / 256, 256>>>(src, dst, et);
    scatter_kernel<<<((size_t)Ee * 32 + 255) / 256, 256>>>(src, dst, et, out);
    finalize_kernel<<<(Nn * D + 255) / 256, 256>>>(out);
}

// round 15
// speedup vs baseline: 1.2153x; 1.2153x over previous
#include <cuda_runtime.h>
#include <cstdint>

#define Nn 50000
#define Ee 500000
#define Rr 200
#define D  128
#define SLOPE 0.01f

// ---------------- device scratch (no allocations allowed) ----------------
__device__ float g_Xa[Nn * D];     // x @ W1a
__device__ float g_Xb[Nn * D];     // x @ W1b + b1
__device__ float g_Relc[Rr * D];   // rel @ W1c
__device__ float g_sa[Nn];         // Xa . w2
__device__ float g_sb[Nn];         // Xb . w2
__device__ float g_sr[Rr];         // Relc . w2
__device__ float g_ex[Ee];         // leaky-relu logits b
__device__ float g_denom[Nn];
__device__ int   g_bmax[Nn];       // encoded float max

__device__ __forceinline__ int fenc(float f) {
    int i = __float_as_int(f);
    return (i >= 0) ? i : (i ^ 0x7FFFFFFF);
}
__device__ __forceinline__ float fdec(int i) {
    return __int_as_float((i >= 0) ? i : (i ^ 0x7FFFFFFF));
}

__device__ __forceinline__ void red_add_v4(float* addr, float4 v) {
    asm volatile("red.global.add.v4.f32 [%0], {%1,%2,%3,%4};"
                 :: "l"(addr), "f"(v.x), "f"(v.y), "f"(v.z), "f"(v.w)
                 : "memory");
}

__device__ __forceinline__ uint32_t f2tf32(float f) {
    uint32_t r;
    asm("cvt.rna.tf32.f32 %0, %1;" : "=r"(r) : "f"(f));
    return r;
}

__device__ __forceinline__ void mma_tf32(float c[4], uint32_t a0, uint32_t a1,
                                         uint32_t a2, uint32_t a3,
                                         uint32_t b0, uint32_t b1) {
    asm volatile(
        "mma.sync.aligned.m16n8k8.row.col.f32.tf32.tf32.f32 "
        "{%0,%1,%2,%3},{%4,%5,%6,%7},{%8,%9},{%0,%1,%2,%3};"
        : "+f"(c[0]), "+f"(c[1]), "+f"(c[2]), "+f"(c[3])
        : "r"(a0), "r"(a1), "r"(a2), "r"(a3), "r"(b0), "r"(b1));
}

// ---------------- init: denom=0, bmax=INT_MIN, sa=sb=0 ----------------
__global__ void init_kernel() {
    int i = blockIdx.x * blockDim.x + threadIdx.x;
    if (i < Nn) {
        g_denom[i] = 0.0f;
        g_bmax[i]  = int(0x80000000);
        g_sa[i]    = 0.0f;
        g_sb[i]    = 0.0f;
    }
}

// ---------------- GEMM (tf32 tensor cores): Xa / Xb = x @ W1[half] --------
// 128x128 tile / block, 256 threads = 8 warps (2 m x 4 n), warp tile 64x32.
// Epilogue stores rows, adds b1 (half==1), and accumulates sa/sb = row . w2.
#define SA 36   // A smem row stride (floats)
#define SB 136  // B smem row stride (floats)
__global__ __launch_bounds__(256) void gemm_xab(const float* __restrict__ x,
                                                const float* __restrict__ W1,
                                                const float* __restrict__ b1,
                                                const float* __restrict__ w2) {
    __shared__ uint32_t As[128 * SA];   // [m][k] 128x32 (+pad)
    __shared__ uint32_t Bs[32 * SB];    // [k][n] 32x128 (+pad)

    const int half = blockIdx.y;
    const int rowBase = blockIdx.x * 128;
    const int tid  = threadIdx.x;
    const int lane = tid & 31;
    const int wid  = tid >> 5;
    const int gid  = lane >> 2;        // 0..7
    const int tig  = lane & 3;         // 0..3
    const int wy   = wid & 1;          // m-warp
    const int wx   = wid >> 1;         // n-warp
    const int m0w  = wy * 64;
    const int n0w  = wx * 32;

    float c[4][4][4];
#pragma unroll
    for (int i = 0; i < 4; i++)
#pragma unroll
        for (int j = 0; j < 4; j++)
#pragma unroll
            for (int r = 0; r < 4; r++) c[i][j][r] = 0.0f;

    // load mappings
    const int am = tid >> 1;               // A row 0..127
    const int ac = (tid & 1) * 16;         // A col base (of 32)
    const int bk = tid >> 3;               // B row 0..31
    const int bc = (tid & 7) * 16;         // B col base (of 128)
    const float* Wbase = W1 + (size_t)half * 128 * 128;
    const bool arow_ok = (rowBase + am) < Nn;

    for (int k0 = 0; k0 < 128; k0 += 32) {
        // ---- load A tile (x) ----
#pragma unroll
        for (int f = 0; f < 4; f++) {
            int col = ac + f * 4;
            float4 v = make_float4(0.f, 0.f, 0.f, 0.f);
            if (arow_ok)
                v = *(const float4*)(x + (size_t)(rowBase + am) * 128 + k0 + col);
            uint4 t = make_uint4(f2tf32(v.x), f2tf32(v.y), f2tf32(v.z), f2tf32(v.w));
            *(uint4*)&As[am * SA + col] = t;
        }
        // ---- load B tile (W1 half) ----
#pragma unroll
        for (int f = 0; f < 4; f++) {
            int col = bc + f * 4;
            float4 v = *(const float4*)(Wbase + (size_t)(k0 + bk) * 128 + col);
            uint4 t = make_uint4(f2tf32(v.x), f2tf32(v.y), f2tf32(v.z), f2tf32(v.w));
            *(uint4*)&Bs[bk * SB + col] = t;
        }
        __syncthreads();

#pragma unroll
        for (int ks = 0; ks < 4; ks++) {
            const int kk = ks * 8;
            uint32_t a[4][4];
#pragma unroll
            for (int i = 0; i < 4; i++) {
                int r0 = (m0w + i * 16 + gid) * SA + kk + tig;
                a[i][0] = As[r0];
                a[i][1] = As[r0 + 8 * SA];
                a[i][2] = As[r0 + 4];
                a[i][3] = As[r0 + 8 * SA + 4];
            }
#pragma unroll
            for (int jj = 0; jj < 4; jj++) {
                int bb = (kk + tig) * SB + n0w + jj * 8 + gid;
                uint32_t b0 = Bs[bb];
                uint32_t b1r = Bs[bb + 4 * SB];
#pragma unroll
                for (int i = 0; i < 4; i++)
                    mma_tf32(c[i][jj], a[i][0], a[i][1], a[i][2], a[i][3], b0, b1r);
            }
        }
        __syncthreads();
    }

    // ---- epilogue: store + fused sa/sb ----
    float* outp = half ? g_Xb : g_Xa;
    float* sp   = half ? g_sb : g_sa;
#pragma unroll
    for (int i = 0; i < 4; i++) {
#pragma unroll
        for (int rh = 0; rh < 2; rh++) {
            int row = rowBase + m0w + i * 16 + rh * 8 + gid;
            float p = 0.f;
            if (row < Nn) {
#pragma unroll
                for (int jj = 0; jj < 4; jj++) {
                    int nb = n0w + jj * 8 + tig * 2;
                    float vx = c[i][jj][rh * 2];
                    float vy = c[i][jj][rh * 2 + 1];
                    if (half) { vx += b1[nb]; vy += b1[nb + 1]; }
                    p += vx * w2[nb] + vy * w2[nb + 1];
                    float2 st = make_float2(vx, vy);
                    *(float2*)&outp[(size_t)row * 128 + nb] = st;
                }
            }
            // reduce over the 4 tig lanes (same gid)
            p += __shfl_xor_sync(0xFFFFFFFFu, p, 1);
            p += __shfl_xor_sync(0xFFFFFFFFu, p, 2);
            if (tig == 0 && row < Nn) atomicAdd(&sp[row], p);
        }
    }
}

// ---------------- Relc = rel @ W1c, sr = Relc . w2 (fp32 exact) -----------
__global__ void relc_kernel(const float* __restrict__ rel,
                            const float* __restrict__ W1,
                            const float* __restrict__ w2) {
    const int r = blockIdx.x;
    const int j = threadIdx.x;              // 128 threads
    __shared__ float rrow[128];
    __shared__ float red[128];
    rrow[j] = rel[(size_t)r * 128 + j];
    __syncthreads();
    const float* Wc = W1 + (size_t)256 * 128;
    float acc = 0.f;
#pragma unroll 8
    for (int k = 0; k < 128; k++) acc += rrow[k] * Wc[(size_t)k * 128 + j];
    g_Relc[(size_t)r * 128 + j] = acc;
    red[j] = acc * w2[j];
    __syncthreads();
    for (int s = 64; s > 0; s >>= 1) {
        if (j < s) red[j] += red[j + s];
        __syncthreads();
    }
    if (j == 0) g_sr[r] = red[0];
}

// ---------------- Pass A: logits + segment max (4 edges per thread) --------
__global__ void logits_max(const int* __restrict__ src, const int* __restrict__ dst,
                           const int* __restrict__ et) {
    int q = blockIdx.x * blockDim.x + threadIdx.x;   // quad index
    if (q >= Ee / 4) return;
    int4 s4 = ((const int4*)src)[q];
    int4 d4 = ((const int4*)dst)[q];
    int4 t4 = ((const int4*)et)[q];
    float b[4];
    {
        float v0 = g_sa[s4.x] + g_sb[d4.x] + g_sr[t4.x];
        float v1 = g_sa[s4.y] + g_sb[d4.y] + g_sr[t4.y];
        float v2 = g_sa[s4.z] + g_sb[d4.z] + g_sr[t4.z];
        float v3 = g_sa[s4.w] + g_sb[d4.w] + g_sr[t4.w];
        b[0] = (v0 > 0.f) ? v0 : SLOPE * v0;
        b[1] = (v1 > 0.f) ? v1 : SLOPE * v1;
        b[2] = (v2 > 0.f) ? v2 : SLOPE * v2;
        b[3] = (v3 > 0.f) ? v3 : SLOPE * v3;
    }
    ((float4*)g_ex)[q] = make_float4(b[0], b[1], b[2], b[3]);
    atomicMax(&g_bmax[d4.x], fenc(b[0]));
    atomicMax(&g_bmax[d4.y], fenc(b[1]));
    atomicMax(&g_bmax[d4.z], fenc(b[2]));
    atomicMax(&g_bmax[d4.w], fenc(b[3]));
}

// ---------------- Pass B+C fused: exp + denom sum + weighted scatter -------
__global__ void scatter_kernel(const int* __restrict__ src, const int* __restrict__ dst,
                               const int* __restrict__ et, float* __restrict__ out) {
    int e = (blockIdx.x * blockDim.x + threadIdx.x) >> 5;
    int lane = threadIdx.x & 31;
    if (e >= Ee) return;
    int s = src[e], d = dst[e], t = et[e];
    float b = g_ex[e];
    float m = fdec(g_bmax[d]);
    float w = expf(b - m);
    if (lane == 0) atomicAdd(&g_denom[d], w);
    float4 xa = *(const float4*)&g_Xa[(size_t)s * 128 + lane * 4];
    float4 rc = *(const float4*)&g_Relc[(size_t)t * 128 + lane * 4];
    float4 v = make_float4(w * (xa.x + rc.x), w * (xa.y + rc.y),
                           w * (xa.z + rc.z), w * (xa.w + rc.w));
    red_add_v4(&out[(size_t)d * 128 + lane * 4], v);
}

// ---------------- finalize: out = leaky(out/denom + Xb) ----------------
__global__ void finalize_kernel(float* __restrict__ out) {
    int idx = blockIdx.x * blockDim.x + threadIdx.x;
    if (idx >= Nn * D) return;
    int n = idx >> 7;
    float dn = g_denom[n];
    float o = 0.f;
    if (dn > 0.f) {
        o = out[idx] / dn + g_Xb[idx];
        o = (o > 0.f) ? o : SLOPE * o;
    }
    out[idx] = o;
}

// ---------------- host launcher ----------------
extern "C" void kernel_launch(void* const* d_in, const int* in_sizes, int n_in,
                              void* d_out, int out_size) {
    const float* x   = (const float*)d_in[0];
    const float* rel = (const float*)d_in[1];
    const float* W1  = (const float*)d_in[2];
    const float* b1  = (const float*)d_in[3];
    const float* w2  = (const float*)d_in[4];
    const int* eidx  = (const int*)d_in[5];
    const int* et    = (const int*)d_in[6];
    const int* src = eidx;
    const int* dst = eidx + Ee;
    float* out = (float*)d_out;

    cudaMemsetAsync(d_out, 0, (size_t)Nn * D * sizeof(float));
    init_kernel<<<(Nn + 255) / 256, 256>>>();
    gemm_xab<<<dim3((Nn + 127) / 128, 2), 256>>>(x, W1, b1, w2);
    relc_kernel<<<Rr, 128>>>(rel, W1, w2);
    logits_max<<<(Ee / 4 + 255) / 256, 256>>>(src, dst, et);
    scatter_kernel<<<((size_t)Ee * 32 + 255) / 256, 256>>>(src, dst, et, out);
    finalize_kernel<<<(Nn * D + 255) / 256, 256>>>(out);
}